// round 1
// baseline (speedup 1.0000x reference)
#include <cuda_runtime.h>
#include <math.h>

#define BATCH 2
#define SEQ 2048
#define DMODEL 1024
#define NHEAD 16
#define DHEAD 64
#define MROWS (BATCH*SEQ)          // 4096
#define NBIAS (2*SEQ-1)            // 4095

// ---------------- scratch (device globals; allocation-free) ----------------
__device__ float g_q[(size_t)BATCH*NHEAD*SEQ*DHEAD];     // [B,H,S,Dh]
__device__ float g_k[(size_t)BATCH*NHEAD*SEQ*DHEAD];
__device__ float g_v[(size_t)BATCH*NHEAD*SEQ*DHEAD];
__device__ float g_attn[(size_t)MROWS*DMODEL];           // [B,S,H*Dh]
__device__ float g_bias[NHEAD*NBIAS];                    // [H][rel+2047]

// ---------------- relative-position bias table ----------------
// Replicates jnp bucket math in fp32, truncating int cast.
__global__ void bias_kernel(const float* __restrict__ rel_emb)
{
    int idx = blockIdx.x * blockDim.x + threadIdx.x;
    if (idx >= NBIAS) return;
    int rel = idx - (SEQ - 1);            // rel = k - q in [-2047, 2047]
    int bucket = (rel > 0) ? 16 : 0;      // nb = num_buckets/2 = 16
    int a = rel < 0 ? -rel : rel;
    if (a < 8) {
        bucket += a;
    } else {
        // max_exact=8, log(max_distance/max_exact)=log(16)
        float t = (logf((float)a / 8.0f) / 2.7725887f) * 8.0f;
        int ti = 8 + (int)t;
        bucket += (ti < 15) ? ti : 15;
    }
    #pragma unroll
    for (int h = 0; h < NHEAD; h++)
        g_bias[h * NBIAS + idx] = rel_emb[bucket * NHEAD + h];
}

// ---------------- SGEMM: C[4096,1024] = A[4096,1024] @ B[1024,1024] ----------------
// mode 0: A := g_attn, write row-major to outp (final projection)
// mode 1/2/3: A := Aparam (hidden_states), write remapped [B,H,S,Dh] to g_q/g_k/g_v
#define BM 128
#define BN 128
#define BK 16
#define TM 8
#define TN 8
#define GK DMODEL
#define GN DMODEL

__global__ __launch_bounds__(256) void sgemm_kernel(
    const float* __restrict__ Aparam, const float* __restrict__ B,
    float* __restrict__ outp, int mode)
{
    __shared__ float As[BK][BM + 4];
    __shared__ float Bs[BK][BN];

    const float* A = (mode == 0) ? (const float*)g_attn : Aparam;

    int tid  = threadIdx.x;
    int brow = blockIdx.y;            // M tile index
    int bcol = blockIdx.x;            // N tile index

    const float* Ab = A + (size_t)brow * BM * GK;
    const float* Bb = B + (size_t)bcol * BN;

    int aRow = tid >> 2;              // 0..63
    int aCol = (tid & 3) << 2;        // 0,4,8,12
    int bRow = tid >> 5;              // 0..7
    int bCol = (tid & 31) << 2;       // 0..124

    float acc[TM][TN];
    #pragma unroll
    for (int i = 0; i < TM; i++)
        #pragma unroll
        for (int j = 0; j < TN; j++) acc[i][j] = 0.f;

    int tr = (tid >> 4) * TM;
    int tc = (tid & 15) * TN;

    for (int k0 = 0; k0 < GK; k0 += BK) {
        #pragma unroll
        for (int i = 0; i < 2; i++) {
            int r = aRow + i * 64;
            float4 v = *(const float4*)(Ab + (size_t)r * GK + k0 + aCol);
            As[aCol + 0][r] = v.x; As[aCol + 1][r] = v.y;
            As[aCol + 2][r] = v.z; As[aCol + 3][r] = v.w;
        }
        #pragma unroll
        for (int i = 0; i < 2; i++) {
            int r = bRow + i * 8;
            *(float4*)(&Bs[r][bCol]) = *(const float4*)(Bb + (size_t)(k0 + r) * GN + bCol);
        }
        __syncthreads();

        #pragma unroll
        for (int kk = 0; kk < BK; kk++) {
            float am[TM], bn[TN];
            #pragma unroll
            for (int i = 0; i < TM; i += 4) *(float4*)&am[i] = *(const float4*)&As[kk][tr + i];
            #pragma unroll
            for (int j = 0; j < TN; j += 4) *(float4*)&bn[j] = *(const float4*)&Bs[kk][tc + j];
            #pragma unroll
            for (int i = 0; i < TM; i++)
                #pragma unroll
                for (int j = 0; j < TN; j++)
                    acc[i][j] += am[i] * bn[j];
        }
        __syncthreads();
    }

    if (mode == 0) {
        #pragma unroll
        for (int i = 0; i < TM; i++) {
            int row = brow * BM + tr + i;
            int col = bcol * BN + tc;
            #pragma unroll
            for (int j = 0; j < TN; j += 4) {
                float4 v; v.x = acc[i][j]; v.y = acc[i][j+1]; v.z = acc[i][j+2]; v.w = acc[i][j+3];
                *(float4*)(outp + (size_t)row * GN + col + j) = v;
            }
        }
    } else {
        float* dst = (mode == 1) ? g_q : (mode == 2) ? g_k : g_v;
        #pragma unroll
        for (int i = 0; i < TM; i++) {
            int row = brow * BM + tr + i;
            int b = row >> 11;               // /SEQ
            int s = row & (SEQ - 1);
            int col = bcol * BN + tc;        // tc multiple of 8 -> stays in one head
            int h = col >> 6;
            int d = col & 63;
            size_t base = (((size_t)(b * NHEAD + h) * SEQ) + s) * DHEAD + d;
            #pragma unroll
            for (int j = 0; j < TN; j += 4) {
                float4 v; v.x = acc[i][j]; v.y = acc[i][j+1]; v.z = acc[i][j+2]; v.w = acc[i][j+3];
                *(float4*)(dst + base + j) = v;
            }
        }
    }
}

// ---------------- flash-style attention ----------------
// grid: (S/64, H, B); 256 threads = 16x16; each thread: 4 q-rows x 4 cols
__global__ __launch_bounds__(256) void attn_kernel()
{
    __shared__ float qs[64 * 64];     // qs[d*64 + r]  (d-major)
    __shared__ float kvs[64 * 64];    // ks[d*64 + c], reused as ps[r*64 + c]
    __shared__ float vs[64 * 64];     // vs[c*64 + d]

    int tid = threadIdx.x;
    int ty = tid >> 4, tx = tid & 15;
    int b = blockIdx.z, h = blockIdx.y;
    int q0 = blockIdx.x * 64;

    const float* Q  = g_q + (size_t)((b * NHEAD + h) * SEQ) * DHEAD;
    const float* Kg = g_k + (size_t)((b * NHEAD + h) * SEQ) * DHEAD;
    const float* Vg = g_v + (size_t)((b * NHEAD + h) * SEQ) * DHEAD;
    const float* bt = g_bias + h * NBIAS + (SEQ - 1);

    // load Q tile transposed -> qs[d][r]
    #pragma unroll
    for (int i = 0; i < 4; i++) {
        int idx = tid + i * 256;
        int r = idx >> 4;
        int d = (idx & 15) << 2;
        float4 t4 = *(const float4*)(Q + (size_t)(q0 + r) * DHEAD + d);
        qs[(d + 0) * 64 + r] = t4.x; qs[(d + 1) * 64 + r] = t4.y;
        qs[(d + 2) * 64 + r] = t4.z; qs[(d + 3) * 64 + r] = t4.w;
    }

    float m[4], l[4], o[4][4];
    #pragma unroll
    for (int i = 0; i < 4; i++) {
        m[i] = -1e30f; l[i] = 0.f;
        #pragma unroll
        for (int j = 0; j < 4; j++) o[i][j] = 0.f;
    }

    for (int kb = 0; kb < SEQ / 64; kb++) {
        __syncthreads();  // previous PV reads done before overwriting tiles
        #pragma unroll
        for (int i = 0; i < 4; i++) {
            int idx = tid + i * 256;
            int r = idx >> 4;
            int d = (idx & 15) << 2;
            float4 t4 = *(const float4*)(Kg + (size_t)(kb * 64 + r) * DHEAD + d);
            kvs[(d + 0) * 64 + r] = t4.x; kvs[(d + 1) * 64 + r] = t4.y;
            kvs[(d + 2) * 64 + r] = t4.z; kvs[(d + 3) * 64 + r] = t4.w;
            float4 v4 = *(const float4*)(Vg + (size_t)(kb * 64 + r) * DHEAD + d);
            *(float4*)&vs[r * 64 + d] = v4;
        }
        __syncthreads();

        // scores: sc[i][j] = sum_d Q[r_i][d] * K[c_j][d]
        float sc[4][4];
        #pragma unroll
        for (int i = 0; i < 4; i++)
            #pragma unroll
            for (int j = 0; j < 4; j++) sc[i][j] = 0.f;

        #pragma unroll
        for (int d = 0; d < 64; d++) {
            float qv[4], kv[4];
            *(float4*)qv = *(const float4*)&qs[d * 64 + ty * 4];
            *(float4*)kv = *(const float4*)&kvs[d * 64 + tx * 4];
            #pragma unroll
            for (int i = 0; i < 4; i++)
                #pragma unroll
                for (int j = 0; j < 4; j++)
                    sc[i][j] += qv[i] * kv[j];
        }

        // bias + online softmax (row = 16 tx threads, width-16 shuffles)
        #pragma unroll
        for (int i = 0; i < 4; i++) {
            int qg = q0 + ty * 4 + i;
            const float* brow = bt + (kb * 64 + tx * 4) - qg;
            float rmax = -1e30f;
            #pragma unroll
            for (int j = 0; j < 4; j++) {
                sc[i][j] += brow[j];
                rmax = fmaxf(rmax, sc[i][j]);
            }
            rmax = fmaxf(rmax, __shfl_xor_sync(0xffffffffu, rmax, 8, 16));
            rmax = fmaxf(rmax, __shfl_xor_sync(0xffffffffu, rmax, 4, 16));
            rmax = fmaxf(rmax, __shfl_xor_sync(0xffffffffu, rmax, 2, 16));
            rmax = fmaxf(rmax, __shfl_xor_sync(0xffffffffu, rmax, 1, 16));
            float mn = fmaxf(m[i], rmax);
            float corr = __expf(m[i] - mn);
            float rs = 0.f;
            #pragma unroll
            for (int j = 0; j < 4; j++) {
                sc[i][j] = __expf(sc[i][j] - mn);
                rs += sc[i][j];
            }
            rs += __shfl_xor_sync(0xffffffffu, rs, 8, 16);
            rs += __shfl_xor_sync(0xffffffffu, rs, 4, 16);
            rs += __shfl_xor_sync(0xffffffffu, rs, 2, 16);
            rs += __shfl_xor_sync(0xffffffffu, rs, 1, 16);
            m[i] = mn;
            l[i] = l[i] * corr + rs;
            #pragma unroll
            for (int j = 0; j < 4; j++) o[i][j] *= corr;
        }

        __syncthreads();  // all score reads of kvs done
        // stage P into kvs as ps[r][c]
        #pragma unroll
        for (int i = 0; i < 4; i++)
            *(float4*)&kvs[(ty * 4 + i) * 64 + tx * 4] = *(float4*)sc[i];
        __syncthreads();

        // o[i][j] += sum_c P[r_i][c] * V[c][d_j]
        #pragma unroll
        for (int c0 = 0; c0 < 64; c0 += 4) {
            float p4[4][4], v4[4][4];
            #pragma unroll
            for (int i = 0; i < 4; i++)
                *(float4*)p4[i] = *(const float4*)&kvs[(ty * 4 + i) * 64 + c0];
            #pragma unroll
            for (int cc = 0; cc < 4; cc++)
                *(float4*)v4[cc] = *(const float4*)&vs[(c0 + cc) * 64 + tx * 4];
            #pragma unroll
            for (int i = 0; i < 4; i++)
                #pragma unroll
                for (int cc = 0; cc < 4; cc++)
                    #pragma unroll
                    for (int j = 0; j < 4; j++)
                        o[i][j] += p4[i][cc] * v4[cc][j];
        }
    }

    // epilogue: normalize, write [B,S,H*Dh]
    #pragma unroll
    for (int i = 0; i < 4; i++) {
        float inv = 1.0f / l[i];
        int qg = q0 + ty * 4 + i;
        float4 r4;
        r4.x = o[i][0] * inv; r4.y = o[i][1] * inv;
        r4.z = o[i][2] * inv; r4.w = o[i][3] * inv;
        *(float4*)&g_attn[(size_t)(b * SEQ + qg) * DMODEL + h * DHEAD + tx * 4] = r4;
    }
}

// ---------------- launch ----------------
extern "C" void kernel_launch(void* const* d_in, const int* in_sizes, int n_in,
                              void* d_out, int out_size)
{
    const float* hs  = (const float*)d_in[0];
    const float* Wq  = (const float*)d_in[1];
    const float* Wk  = (const float*)d_in[2];
    const float* Wv  = (const float*)d_in[3];
    const float* Wo  = (const float*)d_in[4];
    const float* rel = (const float*)d_in[5];
    float* out = (float*)d_out;

    bias_kernel<<<16, 256>>>(rel);

    dim3 ggrid(GN / BN, MROWS / BM);   // (8, 32)
    sgemm_kernel<<<ggrid, 256>>>(hs, Wq, out, 1);
    sgemm_kernel<<<ggrid, 256>>>(hs, Wk, out, 2);
    sgemm_kernel<<<ggrid, 256>>>(hs, Wv, out, 3);

    dim3 agrid(SEQ / 64, NHEAD, BATCH);  // (32, 16, 2)
    attn_kernel<<<agrid, 256>>>();

    sgemm_kernel<<<ggrid, 256>>>(hs /*ignored*/, Wo, out, 0);
}

// round 4
// speedup vs baseline: 2.4215x; 2.4215x over previous
#include <cuda_runtime.h>
#include <cuda_bf16.h>
#include <math.h>
#include <stdint.h>

#define BATCH 2
#define SEQ 2048
#define DMODEL 1024
#define NHEAD 16
#define DHEAD 64
#define MROWS (BATCH*SEQ)          // 4096
#define NBIAS (2*SEQ-1)            // 4095

// ---------------- scratch (device globals; allocation-free) ----------------
__device__ __align__(16) __nv_bfloat16 g_ah[(size_t)MROWS*DMODEL];   // activations hi (hidden, later attn out)
__device__ __align__(16) __nv_bfloat16 g_al[(size_t)MROWS*DMODEL];   // activations lo
__device__ __align__(16) __nv_bfloat16 g_wh[(size_t)4*DMODEL*DMODEL]; // W^T hi, [n][k], 4 mats
__device__ __align__(16) __nv_bfloat16 g_wl[(size_t)4*DMODEL*DMODEL];
__device__ __align__(16) __nv_bfloat16 g_qh[(size_t)BATCH*NHEAD*SEQ*DHEAD];
__device__ __align__(16) __nv_bfloat16 g_ql[(size_t)BATCH*NHEAD*SEQ*DHEAD];
__device__ __align__(16) __nv_bfloat16 g_kh[(size_t)BATCH*NHEAD*SEQ*DHEAD];
__device__ __align__(16) __nv_bfloat16 g_kl[(size_t)BATCH*NHEAD*SEQ*DHEAD];
__device__ __align__(16) __nv_bfloat16 g_vh[(size_t)BATCH*NHEAD*SEQ*DHEAD];
__device__ __align__(16) __nv_bfloat16 g_vl[(size_t)BATCH*NHEAD*SEQ*DHEAD];
__device__ float g_bias[NHEAD*NBIAS];

// ---------------- helpers ----------------
__device__ __forceinline__ uint32_t smem_u32(const void* p) {
    return (uint32_t)__cvta_generic_to_shared(p);
}
__device__ __forceinline__ void ldm4(uint32_t* r, uint32_t a) {
    asm volatile("ldmatrix.sync.aligned.m8n8.x4.shared.b16 {%0,%1,%2,%3}, [%4];"
        : "=r"(r[0]), "=r"(r[1]), "=r"(r[2]), "=r"(r[3]) : "r"(a));
}
__device__ __forceinline__ void ldm4t(uint32_t* r, uint32_t a) {
    asm volatile("ldmatrix.sync.aligned.m8n8.x4.trans.shared.b16 {%0,%1,%2,%3}, [%4];"
        : "=r"(r[0]), "=r"(r[1]), "=r"(r[2]), "=r"(r[3]) : "r"(a));
}
__device__ __forceinline__ void mma16816(float* c, const uint32_t* a, const uint32_t* b) {
    asm volatile("mma.sync.aligned.m16n8k16.row.col.f32.bf16.bf16.f32 "
        "{%0,%1,%2,%3}, {%4,%5,%6,%7}, {%8,%9}, {%0,%1,%2,%3};"
        : "+f"(c[0]), "+f"(c[1]), "+f"(c[2]), "+f"(c[3])
        : "r"(a[0]), "r"(a[1]), "r"(a[2]), "r"(a[3]), "r"(b[0]), "r"(b[1]));
}
// ldmatrix x4 address for 16x16 tile at (R0,C0), row stride lds (bf16 elems)
__device__ __forceinline__ uint32_t ldm_addr(const __nv_bfloat16* base, int lds,
                                             int R0, int C0, int lane) {
    return smem_u32(base + (size_t)(R0 + (lane & 15)) * lds + C0 + ((lane >> 4) << 3));
}
__device__ __forceinline__ void pack_split(float x0, float x1, uint32_t& hi, uint32_t& lo) {
    __nv_bfloat16 h0 = __float2bfloat16_rn(x0), h1 = __float2bfloat16_rn(x1);
    hi = ((uint32_t)__bfloat16_as_ushort(h1) << 16) | (uint32_t)__bfloat16_as_ushort(h0);
    __nv_bfloat16 l0 = __float2bfloat16_rn(x0 - __bfloat162float(h0));
    __nv_bfloat16 l1 = __float2bfloat16_rn(x1 - __bfloat162float(h1));
    lo = ((uint32_t)__bfloat16_as_ushort(l1) << 16) | (uint32_t)__bfloat16_as_ushort(l0);
}

// ---------------- bias table ----------------
__global__ void bias_kernel(const float* __restrict__ rel_emb)
{
    int idx = blockIdx.x * blockDim.x + threadIdx.x;
    if (idx >= NBIAS) return;
    int rel = idx - (SEQ - 1);
    int bucket = (rel > 0) ? 16 : 0;
    int a = rel < 0 ? -rel : rel;
    if (a < 8) {
        bucket += a;
    } else {
        float t = (logf((float)a / 8.0f) / 2.7725887f) * 8.0f;
        int ti = 8 + (int)t;
        bucket += (ti < 15) ? ti : 15;
    }
    #pragma unroll
    for (int h = 0; h < NHEAD; h++)
        g_bias[h * NBIAS + idx] = rel_emb[bucket * NHEAD + h];
}

// ---------------- split hidden -> g_ah/g_al bf16 ----------------
__global__ __launch_bounds__(256) void split_a_kernel(const float* __restrict__ src)
{
    int i = blockIdx.x * blockDim.x + threadIdx.x;  // float4 index
    float4 x = *(const float4*)(src + (size_t)i * 4);
    uint32_t h0, l0, h1, l1;
    pack_split(x.x, x.y, h0, l0);
    pack_split(x.z, x.w, h1, l1);
    uint2 hh = {h0, h1}, ll = {l0, l1};
    *(uint2*)(g_ah + (size_t)i * 4) = hh;
    *(uint2*)(g_al + (size_t)i * 4) = ll;
}

// ---------------- transpose + split W[k][n] -> Wt[n][k] bf16 hi/lo ----------------
__global__ __launch_bounds__(256) void wsplit_kernel(const float* __restrict__ W, int widx)
{
    __shared__ float t[32][33];
    int n0 = blockIdx.x * 32, k0 = blockIdx.y * 32;
    int c = threadIdx.x & 31, r4 = (threadIdx.x >> 5) * 4;
    #pragma unroll
    for (int i = 0; i < 4; i++)
        t[r4 + i][c] = W[(size_t)(k0 + r4 + i) * DMODEL + n0 + c];
    __syncthreads();
    __nv_bfloat16* hi = g_wh + (size_t)widx * DMODEL * DMODEL;
    __nv_bfloat16* lo = g_wl + (size_t)widx * DMODEL * DMODEL;
    #pragma unroll
    for (int i = 0; i < 4; i++) {
        float x = t[c][r4 + i];
        __nv_bfloat16 hb = __float2bfloat16_rn(x);
        size_t o = (size_t)(n0 + r4 + i) * DMODEL + k0 + c;
        hi[o] = hb;
        lo[o] = __float2bfloat16_rn(x - __bfloat162float(hb));
    }
}

// ---------------- mma.sync bf16-split GEMM: C[4096,1024] = A @ W ----------------
// mode 0: write fp32 row-major to outp
// mode 1/2/3: split and write bf16 hi/lo to g_q*/g_k*/g_v* in [B,H,S,Dh]
#define GLDS 40   // BK(32) + 8 pad, bf16 elems

__global__ __launch_bounds__(256, 2) void mma_gemm(float* __restrict__ outp, int mode, int widx)
{
    __shared__ __nv_bfloat16 sm[4 * 128 * GLDS];   // Ah | Al | Bh | Bl
    int tid = threadIdx.x, lane = tid & 31, wid = tid >> 5;
    int brow = blockIdx.y, bcol = blockIdx.x;
    int wm = wid & 1, wn = wid >> 1;               // warp tile: rows wm*64, cols wn*32

    const __nv_bfloat16* srcs[4];
    srcs[0] = g_ah + (size_t)brow * 128 * DMODEL;
    srcs[1] = g_al + (size_t)brow * 128 * DMODEL;
    srcs[2] = g_wh + (size_t)widx * DMODEL * DMODEL + (size_t)bcol * 128 * DMODEL;
    srcs[3] = g_wl + (size_t)widx * DMODEL * DMODEL + (size_t)bcol * 128 * DMODEL;

    float acc[4][4][4];
    #pragma unroll
    for (int i = 0; i < 4; i++)
        #pragma unroll
        for (int j = 0; j < 4; j++)
            #pragma unroll
            for (int k = 0; k < 4; k++) acc[i][j][k] = 0.f;

    for (int k0 = 0; k0 < DMODEL; k0 += 32) {
        __syncthreads();
        #pragma unroll
        for (int t = 0; t < 8; t++) {
            int gid = tid + t * 256;
            int buf = gid >> 9, rem = gid & 511, row = rem >> 2, seg = rem & 3;
            uint4 v = *(const uint4*)(srcs[buf] + (size_t)row * DMODEL + k0 + seg * 8);
            *(uint4*)(&sm[buf * (128 * GLDS) + row * GLDS + seg * 8]) = v;
        }
        __syncthreads();

        #pragma unroll
        for (int ks = 0; ks < 2; ks++) {
            uint32_t ah[4][4], al[4][4];
            #pragma unroll
            for (int mt = 0; mt < 4; mt++) {
                uint32_t a = ldm_addr(sm, GLDS, wm * 64 + mt * 16, ks * 16, lane);
                ldm4(ah[mt], a);
                ldm4(al[mt], a + 128 * GLDS * 2);         // +Al bytes
            }
            #pragma unroll
            for (int ng = 0; ng < 2; ng++) {
                uint32_t bm[4], bl4[4];
                uint32_t ba = ldm_addr(sm + 2 * 128 * GLDS, GLDS, wn * 32 + ng * 16, ks * 16, lane);
                ldm4(bm, ba);
                ldm4(bl4, ba + 128 * GLDS * 2);
                uint32_t bh0[2] = {bm[0], bm[2]},  bh1[2] = {bm[1], bm[3]};
                uint32_t bl0[2] = {bl4[0], bl4[2]}, bl1[2] = {bl4[1], bl4[3]};
                #pragma unroll
                for (int mt = 0; mt < 4; mt++) {
                    mma16816(acc[mt][ng * 2 + 0], ah[mt], bh0);
                    mma16816(acc[mt][ng * 2 + 0], al[mt], bh0);
                    mma16816(acc[mt][ng * 2 + 0], ah[mt], bl0);
                    mma16816(acc[mt][ng * 2 + 1], ah[mt], bh1);
                    mma16816(acc[mt][ng * 2 + 1], al[mt], bh1);
                    mma16816(acc[mt][ng * 2 + 1], ah[mt], bl1);
                }
            }
        }
    }

    // epilogue
    int g = lane >> 2, t2 = (lane & 3) * 2;
    __nv_bfloat16* dh = (mode == 1) ? g_qh : (mode == 2) ? g_kh : g_vh;
    __nv_bfloat16* dl = (mode == 1) ? g_ql : (mode == 2) ? g_kl : g_vl;
    #pragma unroll
    for (int mt = 0; mt < 4; mt++) {
        #pragma unroll
        for (int nt = 0; nt < 4; nt++) {
            int r0  = brow * 128 + wm * 64 + mt * 16 + g;
            int col = bcol * 128 + wn * 32 + nt * 8 + t2;
            float c0 = acc[mt][nt][0], c1 = acc[mt][nt][1];
            float c2 = acc[mt][nt][2], c3 = acc[mt][nt][3];
            if (mode == 0) {
                float2 p0 = {c0, c1}, p1 = {c2, c3};
                *(float2*)(outp + (size_t)r0 * DMODEL + col) = p0;
                *(float2*)(outp + (size_t)(r0 + 8) * DMODEL + col) = p1;
            } else {
                int hh = col >> 6, d = col & 63;
                #pragma unroll
                for (int rr = 0; rr < 2; rr++) {
                    int r = r0 + rr * 8;
                    int b = r >> 11, s = r & (SEQ - 1);
                    size_t o = (((size_t)(b * NHEAD + hh) * SEQ) + s) * DHEAD + d;
                    uint32_t hv, lv;
                    pack_split(rr ? c2 : c0, rr ? c3 : c1, hv, lv);
                    *(uint32_t*)(dh + o) = hv;
                    *(uint32_t*)(dl + o) = lv;
                }
            }
        }
    }
}

// ---------------- mma.sync flash attention ----------------
// CTA: 128 q-rows for one (b,h); 8 warps x 16 rows; loop over 64-key tiles.
#define QLDS 72
#define ATT_SMEM (2*128*QLDS*2 + 4*64*QLDS*2 + 192*4)

__global__ __launch_bounds__(256, 2) void mma_attn()
{
    extern __shared__ char smemraw[];
    __nv_bfloat16* sQh = (__nv_bfloat16*)smemraw;          // 128 x 72
    __nv_bfloat16* sQl = sQh + 128 * QLDS;
    __nv_bfloat16* sKh = sQl + 128 * QLDS;                 // 64 x 72, then Kl,Vh,Vl contiguous
    float* sBias = (float*)(sKh + 4 * 64 * QLDS);

    int tid = threadIdx.x, lane = tid & 31, wid = tid >> 5;
    int b = blockIdx.z, h = blockIdx.y, q0 = blockIdx.x * 128;
    size_t bh = (size_t)(b * NHEAD + h) * SEQ;

    // load Q tile (hi/lo)
    #pragma unroll
    for (int t = 0; t < 8; t++) {
        int gid = tid + t * 256;
        int buf = gid >> 10, rem = gid & 1023, row = rem >> 3, seg = rem & 7;
        const __nv_bfloat16* src = (buf ? g_ql : g_qh) + (bh + q0 + row) * DHEAD + seg * 8;
        __nv_bfloat16* dst = (buf ? sQl : sQh) + row * QLDS + seg * 8;
        *(uint4*)dst = *(const uint4*)src;
    }
    __syncthreads();

    // persistent Q-hi fragments
    uint32_t qh[4][4];
    #pragma unroll
    for (int ks = 0; ks < 4; ks++)
        ldm4(qh[ks], ldm_addr(sQh, QLDS, wid * 16, ks * 16, lane));

    int g = lane >> 2, t2 = (lane & 3) * 2;
    int qloc0 = wid * 16 + g, qloc1 = qloc0 + 8;
    float m0 = -1e30f, m1 = -1e30f, l0 = 0.f, l1 = 0.f;
    float acco[8][4];
    #pragma unroll
    for (int i = 0; i < 8; i++)
        #pragma unroll
        for (int j = 0; j < 4; j++) acco[i][j] = 0.f;

    for (int kb = 0; kb < SEQ / 64; kb++) {
        __syncthreads();
        #pragma unroll
        for (int t = 0; t < 8; t++) {
            int gid = tid + t * 256;
            int buf = gid >> 9, rem = gid & 511, row = rem >> 3, seg = rem & 7;
            const __nv_bfloat16* src =
                ((buf == 0) ? g_kh : (buf == 1) ? g_kl : (buf == 2) ? g_vh : g_vl)
                + (bh + kb * 64 + row) * DHEAD + seg * 8;
            *(uint4*)(sKh + buf * (64 * QLDS) + row * QLDS + seg * 8) = *(const uint4*)src;
        }
        if (tid < 191)
            sBias[tid] = g_bias[h * NBIAS + (SEQ - 1) + kb * 64 - q0 - 127 + tid];
        __syncthreads();

        // ---- scores = Q K^T (3-pass split) ----
        float accs[8][4];
        #pragma unroll
        for (int i = 0; i < 8; i++)
            #pragma unroll
            for (int j = 0; j < 4; j++) accs[i][j] = 0.f;

        #pragma unroll
        for (int ks = 0; ks < 4; ks++) {
            uint32_t ql[4];
            ldm4(ql, ldm_addr(sQl, QLDS, wid * 16, ks * 16, lane));
            #pragma unroll
            for (int ng = 0; ng < 4; ng++) {
                uint32_t km[4], kl4[4];
                uint32_t ka = ldm_addr(sKh, QLDS, ng * 16, ks * 16, lane);
                ldm4(km, ka);
                ldm4(kl4, ka + 64 * QLDS * 2);
                uint32_t kh0[2] = {km[0], km[2]},  kh1[2] = {km[1], km[3]};
                uint32_t kl0[2] = {kl4[0], kl4[2]}, kl1[2] = {kl4[1], kl4[3]};
                mma16816(accs[ng * 2 + 0], qh[ks], kh0);
                mma16816(accs[ng * 2 + 0], ql,     kh0);
                mma16816(accs[ng * 2 + 0], qh[ks], kl0);
                mma16816(accs[ng * 2 + 1], qh[ks], kh1);
                mma16816(accs[ng * 2 + 1], ql,     kh1);
                mma16816(accs[ng * 2 + 1], qh[ks], kl1);
            }
        }

        // ---- bias + online softmax ----
        float rmax0 = -1e30f, rmax1 = -1e30f;
        #pragma unroll
        for (int nt = 0; nt < 8; nt++) {
            int c = nt * 8 + t2;
            accs[nt][0] += sBias[c + 127 - qloc0];
            accs[nt][1] += sBias[c + 128 - qloc0];
            accs[nt][2] += sBias[c + 127 - qloc1];
            accs[nt][3] += sBias[c + 128 - qloc1];
            rmax0 = fmaxf(rmax0, fmaxf(accs[nt][0], accs[nt][1]));
            rmax1 = fmaxf(rmax1, fmaxf(accs[nt][2], accs[nt][3]));
        }
        rmax0 = fmaxf(rmax0, __shfl_xor_sync(0xffffffffu, rmax0, 1, 4));
        rmax0 = fmaxf(rmax0, __shfl_xor_sync(0xffffffffu, rmax0, 2, 4));
        rmax1 = fmaxf(rmax1, __shfl_xor_sync(0xffffffffu, rmax1, 1, 4));
        rmax1 = fmaxf(rmax1, __shfl_xor_sync(0xffffffffu, rmax1, 2, 4));
        float mn0 = fmaxf(m0, rmax0), mn1 = fmaxf(m1, rmax1);
        float corr0 = __expf(m0 - mn0), corr1 = __expf(m1 - mn1);
        float sum0 = 0.f, sum1 = 0.f;
        #pragma unroll
        for (int nt = 0; nt < 8; nt++) {
            accs[nt][0] = __expf(accs[nt][0] - mn0);
            accs[nt][1] = __expf(accs[nt][1] - mn0);
            accs[nt][2] = __expf(accs[nt][2] - mn1);
            accs[nt][3] = __expf(accs[nt][3] - mn1);
            sum0 += accs[nt][0] + accs[nt][1];
            sum1 += accs[nt][2] + accs[nt][3];
        }
        sum0 += __shfl_xor_sync(0xffffffffu, sum0, 1, 4);
        sum0 += __shfl_xor_sync(0xffffffffu, sum0, 2, 4);
        sum1 += __shfl_xor_sync(0xffffffffu, sum1, 1, 4);
        sum1 += __shfl_xor_sync(0xffffffffu, sum1, 2, 4);
        m0 = mn0; m1 = mn1;
        l0 = l0 * corr0 + sum0;
        l1 = l1 * corr1 + sum1;
        #pragma unroll
        for (int nt = 0; nt < 8; nt++) {
            acco[nt][0] *= corr0; acco[nt][1] *= corr0;
            acco[nt][2] *= corr1; acco[nt][3] *= corr1;
        }

        // ---- out += P V (3-pass split); P packed from score frags ----
        #pragma unroll
        for (int ks = 0; ks < 4; ks++) {
            uint32_t ph[4], pl[4];
            pack_split(accs[2 * ks][0],     accs[2 * ks][1],     ph[0], pl[0]);
            pack_split(accs[2 * ks][2],     accs[2 * ks][3],     ph[1], pl[1]);
            pack_split(accs[2 * ks + 1][0], accs[2 * ks + 1][1], ph[2], pl[2]);
            pack_split(accs[2 * ks + 1][2], accs[2 * ks + 1][3], ph[3], pl[3]);
            #pragma unroll
            for (int dg = 0; dg < 4; dg++) {
                uint32_t vm[4], vl4[4];
                uint32_t va = ldm_addr(sKh + 2 * 64 * QLDS, QLDS, ks * 16, dg * 16, lane);
                ldm4t(vm, va);
                ldm4t(vl4, va + 64 * QLDS * 2);
                uint32_t vh0[2] = {vm[0], vm[1]},  vh1[2] = {vm[2], vm[3]};
                uint32_t vl0[2] = {vl4[0], vl4[1]}, vl1[2] = {vl4[2], vl4[3]};
                mma16816(acco[dg * 2 + 0], ph, vh0);
                mma16816(acco[dg * 2 + 0], pl, vh0);
                mma16816(acco[dg * 2 + 0], ph, vl0);
                mma16816(acco[dg * 2 + 1], ph, vh1);
                mma16816(acco[dg * 2 + 1], pl, vh1);
                mma16816(acco[dg * 2 + 1], ph, vl1);
            }
        }
    }

    // ---- epilogue: normalize, split, write to g_ah/g_al [B,S,H*Dh] ----
    float inv0 = 1.0f / l0, inv1 = 1.0f / l1;
    int row0 = b * SEQ + q0 + wid * 16 + g;
    #pragma unroll
    for (int dt = 0; dt < 8; dt++) {
        int d = h * DHEAD + dt * 8 + t2;
        uint32_t hv, lv;
        pack_split(acco[dt][0] * inv0, acco[dt][1] * inv0, hv, lv);
        *(uint32_t*)(g_ah + (size_t)row0 * DMODEL + d) = hv;
        *(uint32_t*)(g_al + (size_t)row0 * DMODEL + d) = lv;
        pack_split(acco[dt][2] * inv1, acco[dt][3] * inv1, hv, lv);
        *(uint32_t*)(g_ah + (size_t)(row0 + 8) * DMODEL + d) = hv;
        *(uint32_t*)(g_al + (size_t)(row0 + 8) * DMODEL + d) = lv;
    }
}

// ---------------- launch ----------------
extern "C" void kernel_launch(void* const* d_in, const int* in_sizes, int n_in,
                              void* d_out, int out_size)
{
    const float* hs  = (const float*)d_in[0];
    const float* Wq  = (const float*)d_in[1];
    const float* Wk  = (const float*)d_in[2];
    const float* Wv  = (const float*)d_in[3];
    const float* Wo  = (const float*)d_in[4];
    const float* rel = (const float*)d_in[5];
    float* out = (float*)d_out;

    cudaFuncSetAttribute(mma_attn, cudaFuncAttributeMaxDynamicSharedMemorySize, ATT_SMEM);

    bias_kernel<<<16, 256>>>(rel);
    split_a_kernel<<<(MROWS * DMODEL) / (256 * 4), 256>>>(hs);
    dim3 wgrid(32, 32);
    wsplit_kernel<<<wgrid, 256>>>(Wq, 0);
    wsplit_kernel<<<wgrid, 256>>>(Wk, 1);
    wsplit_kernel<<<wgrid, 256>>>(Wv, 2);
    wsplit_kernel<<<wgrid, 256>>>(Wo, 3);

    dim3 ggrid(DMODEL / 128, MROWS / 128);   // (8, 32)
    mma_gemm<<<ggrid, 256>>>(out, 1, 0);
    mma_gemm<<<ggrid, 256>>>(out, 2, 1);
    mma_gemm<<<ggrid, 256>>>(out, 3, 2);

    dim3 agrid(SEQ / 128, NHEAD, BATCH);     // (16, 16, 2)
    mma_attn<<<agrid, 256, ATT_SMEM>>>();

    mma_gemm<<<ggrid, 256>>>(out, 0, 3);     // reads g_ah/g_al written by attention
}

// round 6
// speedup vs baseline: 2.4944x; 1.0301x over previous
#include <cuda_runtime.h>
#include <cuda_bf16.h>
#include <math.h>
#include <stdint.h>

#define BATCH 2
#define SEQ 2048
#define DMODEL 1024
#define NHEAD 16
#define DHEAD 64
#define MROWS (BATCH*SEQ)          // 4096
#define NBIAS (2*SEQ-1)            // 4095

// ---------------- scratch (device globals; allocation-free) ----------------
__device__ __align__(16) __nv_bfloat16 g_ah[(size_t)MROWS*DMODEL];
__device__ __align__(16) __nv_bfloat16 g_al[(size_t)MROWS*DMODEL];
__device__ __align__(16) __nv_bfloat16 g_wh[(size_t)4*DMODEL*DMODEL];
__device__ __align__(16) __nv_bfloat16 g_wl[(size_t)4*DMODEL*DMODEL];
__device__ __align__(16) __nv_bfloat16 g_qh[(size_t)BATCH*NHEAD*SEQ*DHEAD];
__device__ __align__(16) __nv_bfloat16 g_ql[(size_t)BATCH*NHEAD*SEQ*DHEAD];
__device__ __align__(16) __nv_bfloat16 g_kh[(size_t)BATCH*NHEAD*SEQ*DHEAD];
__device__ __align__(16) __nv_bfloat16 g_kl[(size_t)BATCH*NHEAD*SEQ*DHEAD];
__device__ __align__(16) __nv_bfloat16 g_vh[(size_t)BATCH*NHEAD*SEQ*DHEAD];
__device__ __align__(16) __nv_bfloat16 g_vl[(size_t)BATCH*NHEAD*SEQ*DHEAD];
__device__ float g_bias[NHEAD*NBIAS];

// ---------------- helpers ----------------
__device__ __forceinline__ uint32_t smem_u32(const void* p) {
    return (uint32_t)__cvta_generic_to_shared(p);
}
__device__ __forceinline__ void ldm4(uint32_t* r, uint32_t a) {
    asm volatile("ldmatrix.sync.aligned.m8n8.x4.shared.b16 {%0,%1,%2,%3}, [%4];"
        : "=r"(r[0]), "=r"(r[1]), "=r"(r[2]), "=r"(r[3]) : "r"(a));
}
__device__ __forceinline__ void ldm4t(uint32_t* r, uint32_t a) {
    asm volatile("ldmatrix.sync.aligned.m8n8.x4.trans.shared.b16 {%0,%1,%2,%3}, [%4];"
        : "=r"(r[0]), "=r"(r[1]), "=r"(r[2]), "=r"(r[3]) : "r"(a));
}
__device__ __forceinline__ void mma16816(float* c, const uint32_t* a, const uint32_t* b) {
    asm volatile("mma.sync.aligned.m16n8k16.row.col.f32.bf16.bf16.f32 "
        "{%0,%1,%2,%3}, {%4,%5,%6,%7}, {%8,%9}, {%0,%1,%2,%3};"
        : "+f"(c[0]), "+f"(c[1]), "+f"(c[2]), "+f"(c[3])
        : "r"(a[0]), "r"(a[1]), "r"(a[2]), "r"(a[3]), "r"(b[0]), "r"(b[1]));
}
__device__ __forceinline__ uint32_t ldm_addr(const __nv_bfloat16* base, int lds,
                                             int R0, int C0, int lane) {
    return smem_u32(base + (size_t)(R0 + (lane & 15)) * lds + C0 + ((lane >> 4) << 3));
}
__device__ __forceinline__ void pack_split(float x0, float x1, uint32_t& hi, uint32_t& lo) {
    __nv_bfloat16 h0 = __float2bfloat16_rn(x0), h1 = __float2bfloat16_rn(x1);
    hi = ((uint32_t)__bfloat16_as_ushort(h1) << 16) | (uint32_t)__bfloat16_as_ushort(h0);
    __nv_bfloat16 l0 = __float2bfloat16_rn(x0 - __bfloat162float(h0));
    __nv_bfloat16 l1 = __float2bfloat16_rn(x1 - __bfloat162float(h1));
    lo = ((uint32_t)__bfloat16_as_ushort(l1) << 16) | (uint32_t)__bfloat16_as_ushort(l0);
}
__device__ __forceinline__ void cpasync16(uint32_t dst, const void* src) {
    asm volatile("cp.async.cg.shared.global [%0], [%1], 16;" :: "r"(dst), "l"(src));
}
__device__ __forceinline__ void cpcommit() { asm volatile("cp.async.commit_group;"); }
__device__ __forceinline__ void cpwait1()  { asm volatile("cp.async.wait_group 1;"); }
__device__ __forceinline__ void cpwait0()  { asm volatile("cp.async.wait_group 0;"); }

// ---------------- bias table ----------------
__global__ void bias_kernel(const float* __restrict__ rel_emb)
{
    int idx = blockIdx.x * blockDim.x + threadIdx.x;
    if (idx >= NBIAS) return;
    int rel = idx - (SEQ - 1);
    int bucket = (rel > 0) ? 16 : 0;
    int a = rel < 0 ? -rel : rel;
    if (a < 8) {
        bucket += a;
    } else {
        float t = (logf((float)a / 8.0f) / 2.7725887f) * 8.0f;
        int ti = 8 + (int)t;
        bucket += (ti < 15) ? ti : 15;
    }
    #pragma unroll
    for (int h = 0; h < NHEAD; h++)
        g_bias[h * NBIAS + idx] = rel_emb[bucket * NHEAD + h];
}

// ---------------- split hidden -> g_ah/g_al bf16 ----------------
__global__ __launch_bounds__(256) void split_a_kernel(const float* __restrict__ src)
{
    int i = blockIdx.x * blockDim.x + threadIdx.x;
    float4 x = *(const float4*)(src + (size_t)i * 4);
    uint32_t h0, l0, h1, l1;
    pack_split(x.x, x.y, h0, l0);
    pack_split(x.z, x.w, h1, l1);
    uint2 hh = {h0, h1}, ll = {l0, l1};
    *(uint2*)(g_ah + (size_t)i * 4) = hh;
    *(uint2*)(g_al + (size_t)i * 4) = ll;
}

// ---------------- transpose + split W[k][n] -> Wt[n][k] ----------------
__global__ __launch_bounds__(256) void wsplit_kernel(const float* __restrict__ W, int widx)
{
    __shared__ float t[32][33];
    int n0 = blockIdx.x * 32, k0 = blockIdx.y * 32;
    int c = threadIdx.x & 31, r4 = (threadIdx.x >> 5) * 4;
    #pragma unroll
    for (int i = 0; i < 4; i++)
        t[r4 + i][c] = W[(size_t)(k0 + r4 + i) * DMODEL + n0 + c];
    __syncthreads();
    __nv_bfloat16* hi = g_wh + (size_t)widx * DMODEL * DMODEL;
    __nv_bfloat16* lo = g_wl + (size_t)widx * DMODEL * DMODEL;
    #pragma unroll
    for (int i = 0; i < 4; i++) {
        float x = t[c][r4 + i];
        __nv_bfloat16 hb = __float2bfloat16_rn(x);
        size_t o = (size_t)(n0 + r4 + i) * DMODEL + k0 + c;
        hi[o] = hb;
        lo[o] = __float2bfloat16_rn(x - __bfloat162float(hb));
    }
}

// ---------------- pipelined mma.sync bf16-split GEMM ----------------
#define GLDS 40
#define GSTAGE (128 * GLDS)                 // elems per buffer
#define GS_BYTES (2 * 4 * GSTAGE * 2)       // 2 stages x 4 buffers

__global__ __launch_bounds__(256, 2) void mma_gemm(float* __restrict__ outp, int mode, int widx)
{
    extern __shared__ __nv_bfloat16 smp[];
    int tid = threadIdx.x, lane = tid & 31, wid = tid >> 5;
    int brow = blockIdx.y, bcol = blockIdx.x;
    int wm = wid & 1, wn = wid >> 1;

    const __nv_bfloat16* srcs[4];
    srcs[0] = g_ah + (size_t)brow * 128 * DMODEL;
    srcs[1] = g_al + (size_t)brow * 128 * DMODEL;
    srcs[2] = g_wh + (size_t)widx * DMODEL * DMODEL + (size_t)bcol * 128 * DMODEL;
    srcs[3] = g_wl + (size_t)widx * DMODEL * DMODEL + (size_t)bcol * 128 * DMODEL;

    int lbuf[8], lrow[8], lseg[8];
    #pragma unroll
    for (int t = 0; t < 8; t++) {
        int gid = tid + t * 256;
        lbuf[t] = gid >> 9; lrow[t] = (gid >> 2) & 127; lseg[t] = gid & 3;
    }

    float acc[4][4][4];
    #pragma unroll
    for (int i = 0; i < 4; i++)
        #pragma unroll
        for (int j = 0; j < 4; j++)
            #pragma unroll
            for (int k = 0; k < 4; k++) acc[i][j][k] = 0.f;

    #pragma unroll
    for (int t = 0; t < 8; t++) {
        uint32_t dst = smem_u32(&smp[lbuf[t] * GSTAGE + lrow[t] * GLDS + lseg[t] * 8]);
        cpasync16(dst, srcs[lbuf[t]] + (size_t)lrow[t] * DMODEL + lseg[t] * 8);
    }
    cpcommit();

    for (int it = 0; it < DMODEL / 32; it++) {
        int s = it & 1;
        if (it + 1 < DMODEL / 32) {
            int k0 = (it + 1) * 32;
            #pragma unroll
            for (int t = 0; t < 8; t++) {
                uint32_t dst = smem_u32(&smp[(s ^ 1) * 4 * GSTAGE + lbuf[t] * GSTAGE + lrow[t] * GLDS + lseg[t] * 8]);
                cpasync16(dst, srcs[lbuf[t]] + (size_t)lrow[t] * DMODEL + k0 + lseg[t] * 8);
            }
            cpcommit();
            cpwait1();
        } else {
            cpwait0();
        }
        __syncthreads();

        const __nv_bfloat16* sm = smp + s * 4 * GSTAGE;
        #pragma unroll
        for (int ks = 0; ks < 2; ks++) {
            uint32_t ah[4][4], al[4][4];
            #pragma unroll
            for (int mt = 0; mt < 4; mt++) {
                uint32_t a = ldm_addr(sm, GLDS, wm * 64 + mt * 16, ks * 16, lane);
                ldm4(ah[mt], a);
                ldm4(al[mt], a + GSTAGE * 2);
            }
            #pragma unroll
            for (int ng = 0; ng < 2; ng++) {
                uint32_t bm[4], bl4[4];
                uint32_t ba = ldm_addr(sm + 2 * GSTAGE, GLDS, wn * 32 + ng * 16, ks * 16, lane);
                ldm4(bm, ba);
                ldm4(bl4, ba + GSTAGE * 2);
                uint32_t bh0[2] = {bm[0], bm[2]},  bh1[2] = {bm[1], bm[3]};
                uint32_t bl0[2] = {bl4[0], bl4[2]}, bl1[2] = {bl4[1], bl4[3]};
                #pragma unroll
                for (int mt = 0; mt < 4; mt++) {
                    mma16816(acc[mt][ng * 2 + 0], ah[mt], bh0);
                    mma16816(acc[mt][ng * 2 + 0], al[mt], bh0);
                    mma16816(acc[mt][ng * 2 + 0], ah[mt], bl0);
                    mma16816(acc[mt][ng * 2 + 1], ah[mt], bh1);
                    mma16816(acc[mt][ng * 2 + 1], al[mt], bh1);
                    mma16816(acc[mt][ng * 2 + 1], ah[mt], bl1);
                }
            }
        }
        __syncthreads();
    }

    int g = lane >> 2, t2 = (lane & 3) * 2;
    __nv_bfloat16* dh = (mode == 1) ? g_qh : (mode == 2) ? g_kh : g_vh;
    __nv_bfloat16* dl = (mode == 1) ? g_ql : (mode == 2) ? g_kl : g_vl;
    #pragma unroll
    for (int mt = 0; mt < 4; mt++) {
        #pragma unroll
        for (int nt = 0; nt < 4; nt++) {
            int r0  = brow * 128 + wm * 64 + mt * 16 + g;
            int col = bcol * 128 + wn * 32 + nt * 8 + t2;
            float c0 = acc[mt][nt][0], c1 = acc[mt][nt][1];
            float c2 = acc[mt][nt][2], c3 = acc[mt][nt][3];
            if (mode == 0) {
                float2 p0 = {c0, c1}, p1 = {c2, c3};
                *(float2*)(outp + (size_t)r0 * DMODEL + col) = p0;
                *(float2*)(outp + (size_t)(r0 + 8) * DMODEL + col) = p1;
            } else {
                int hh = col >> 6, d = col & 63;
                #pragma unroll
                for (int rr = 0; rr < 2; rr++) {
                    int r = r0 + rr * 8;
                    int b = r >> 11, s = r & (SEQ - 1);
                    size_t o = (((size_t)(b * NHEAD + hh) * SEQ) + s) * DHEAD + d;
                    uint32_t hv, lv;
                    pack_split(rr ? c2 : c0, rr ? c3 : c1, hv, lv);
                    *(uint32_t*)(dh + o) = hv;
                    *(uint32_t*)(dl + o) = lv;
                }
            }
        }
    }
}

// ---------------- pipelined mma.sync flash attention ----------------
#define QLDS 72
#define KVSTAGE (4 * 64 * QLDS)   // elems per stage (Kh|Kl|Vh|Vl)
#define ATT_SMEM (2*128*QLDS*2 + 2*KVSTAGE*2 + 2*192*4)

__global__ __launch_bounds__(256, 2) void mma_attn()
{
    extern __shared__ char smemraw[];
    __nv_bfloat16* sQh = (__nv_bfloat16*)smemraw;          // 128 x 72
    __nv_bfloat16* sQl = sQh + 128 * QLDS;
    __nv_bfloat16* sKV = sQl + 128 * QLDS;                 // 2 stages x (Kh|Kl|Vh|Vl)
    float* sBias = (float*)(sKV + 2 * KVSTAGE);            // 2 x 192

    int tid = threadIdx.x, lane = tid & 31, wid = tid >> 5;
    int b = blockIdx.z, h = blockIdx.y, q0 = blockIdx.x * 128;
    size_t bh = (size_t)(b * NHEAD + h) * SEQ;

    const __nv_bfloat16* kvsrc[4] = {g_kh, g_kl, g_vh, g_vl};

    // load Q tile (hi/lo), once
    #pragma unroll
    for (int t = 0; t < 8; t++) {
        int gid = tid + t * 256;
        int buf = gid >> 10, rem = gid & 1023, row = rem >> 3, seg = rem & 7;
        const __nv_bfloat16* src = (buf ? g_ql : g_qh) + (bh + q0 + row) * DHEAD + seg * 8;
        *(uint4*)((buf ? sQl : sQh) + row * QLDS + seg * 8) = *(const uint4*)src;
    }

    int vbuf[8], vrow[8], vseg[8];
    #pragma unroll
    for (int t = 0; t < 8; t++) {
        int gid = tid + t * 256;
        vbuf[t] = gid >> 9; vrow[t] = (gid >> 3) & 63; vseg[t] = gid & 7;
    }

    // issue KV tile 0 into stage 0 (+ bias)
    #pragma unroll
    for (int t = 0; t < 8; t++) {
        uint32_t dst = smem_u32(sKV + vbuf[t] * (64 * QLDS) + vrow[t] * QLDS + vseg[t] * 8);
        cpasync16(dst, kvsrc[vbuf[t]] + (bh + vrow[t]) * DHEAD + vseg[t] * 8);
    }
    cpcommit();
    if (tid < 191)
        sBias[tid] = g_bias[h * NBIAS + (SEQ - 1) - q0 - 127 + tid];
    __syncthreads();

    // persistent Q fragments (hi and lo)
    uint32_t qh[4][4], ql[4][4];
    #pragma unroll
    for (int ks = 0; ks < 4; ks++) {
        uint32_t a = ldm_addr(sQh, QLDS, wid * 16, ks * 16, lane);
        ldm4(qh[ks], a);
        ldm4(ql[ks], a + 128 * QLDS * 2);
    }

    int g = lane >> 2, t2 = (lane & 3) * 2;
    int qloc0 = wid * 16 + g, qloc1 = qloc0 + 8;
    float m0 = -1e30f, m1 = -1e30f, l0 = 0.f, l1 = 0.f;
    float acco[8][4];
    #pragma unroll
    for (int i = 0; i < 8; i++)
        #pragma unroll
        for (int j = 0; j < 4; j++) acco[i][j] = 0.f;

    for (int kb = 0; kb < SEQ / 64; kb++) {
        int s = kb & 1;
        if (kb + 1 < SEQ / 64) {
            #pragma unroll
            for (int t = 0; t < 8; t++) {
                uint32_t dst = smem_u32(sKV + (s ^ 1) * KVSTAGE + vbuf[t] * (64 * QLDS) + vrow[t] * QLDS + vseg[t] * 8);
                cpasync16(dst, kvsrc[vbuf[t]] + (bh + (kb + 1) * 64 + vrow[t]) * DHEAD + vseg[t] * 8);
            }
            cpcommit();
            if (tid < 191)
                sBias[(s ^ 1) * 192 + tid] = g_bias[h * NBIAS + (SEQ - 1) + (kb + 1) * 64 - q0 - 127 + tid];
            cpwait1();
        } else {
            cpwait0();
        }
        __syncthreads();

        const __nv_bfloat16* sKh = sKV + s * KVSTAGE;
        const float* bias = sBias + s * 192;

        float accs[8][4];
        #pragma unroll
        for (int i = 0; i < 8; i++)
            #pragma unroll
            for (int j = 0; j < 4; j++) accs[i][j] = 0.f;

        #pragma unroll
        for (int ks = 0; ks < 4; ks++) {
            #pragma unroll
            for (int ng = 0; ng < 4; ng++) {
                uint32_t km[4], kl4[4];
                uint32_t ka = ldm_addr(sKh, QLDS, ng * 16, ks * 16, lane);
                ldm4(km, ka);
                ldm4(kl4, ka + 64 * QLDS * 2);
                uint32_t kh0[2] = {km[0], km[2]},  kh1[2] = {km[1], km[3]};
                uint32_t kl0[2] = {kl4[0], kl4[2]}, kl1[2] = {kl4[1], kl4[3]};
                mma16816(accs[ng * 2 + 0], qh[ks], kh0);
                mma16816(accs[ng * 2 + 0], ql[ks], kh0);
                mma16816(accs[ng * 2 + 0], qh[ks], kl0);
                mma16816(accs[ng * 2 + 1], qh[ks], kh1);
                mma16816(accs[ng * 2 + 1], ql[ks], kh1);
                mma16816(accs[ng * 2 + 1], qh[ks], kl1);
            }
        }

        float rmax0 = -1e30f, rmax1 = -1e30f;
        #pragma unroll
        for (int nt = 0; nt < 8; nt++) {
            int c = nt * 8 + t2;
            accs[nt][0] += bias[c + 127 - qloc0];
            accs[nt][1] += bias[c + 128 - qloc0];
            accs[nt][2] += bias[c + 127 - qloc1];
            accs[nt][3] += bias[c + 128 - qloc1];
            rmax0 = fmaxf(rmax0, fmaxf(accs[nt][0], accs[nt][1]));
            rmax1 = fmaxf(rmax1, fmaxf(accs[nt][2], accs[nt][3]));
        }
        rmax0 = fmaxf(rmax0, __shfl_xor_sync(0xffffffffu, rmax0, 1, 4));
        rmax0 = fmaxf(rmax0, __shfl_xor_sync(0xffffffffu, rmax0, 2, 4));
        rmax1 = fmaxf(rmax1, __shfl_xor_sync(0xffffffffu, rmax1, 1, 4));
        rmax1 = fmaxf(rmax1, __shfl_xor_sync(0xffffffffu, rmax1, 2, 4));
        float mn0 = fmaxf(m0, rmax0), mn1 = fmaxf(m1, rmax1);
        float corr0 = __expf(m0 - mn0), corr1 = __expf(m1 - mn1);
        float sum0 = 0.f, sum1 = 0.f;
        #pragma unroll
        for (int nt = 0; nt < 8; nt++) {
            accs[nt][0] = __expf(accs[nt][0] - mn0);
            accs[nt][1] = __expf(accs[nt][1] - mn0);
            accs[nt][2] = __expf(accs[nt][2] - mn1);
            accs[nt][3] = __expf(accs[nt][3] - mn1);
            sum0 += accs[nt][0] + accs[nt][1];
            sum1 += accs[nt][2] + accs[nt][3];
        }
        sum0 += __shfl_xor_sync(0xffffffffu, sum0, 1, 4);
        sum0 += __shfl_xor_sync(0xffffffffu, sum0, 2, 4);
        sum1 += __shfl_xor_sync(0xffffffffu, sum1, 1, 4);
        sum1 += __shfl_xor_sync(0xffffffffu, sum1, 2, 4);
        m0 = mn0; m1 = mn1;
        l0 = l0 * corr0 + sum0;
        l1 = l1 * corr1 + sum1;
        #pragma unroll
        for (int nt = 0; nt < 8; nt++) {
            acco[nt][0] *= corr0; acco[nt][1] *= corr0;
            acco[nt][2] *= corr1; acco[nt][3] *= corr1;
        }

        #pragma unroll
        for (int ks = 0; ks < 4; ks++) {
            uint32_t ph[4], pl[4];
            pack_split(accs[2 * ks][0],     accs[2 * ks][1],     ph[0], pl[0]);
            pack_split(accs[2 * ks][2],     accs[2 * ks][3],     ph[1], pl[1]);
            pack_split(accs[2 * ks + 1][0], accs[2 * ks + 1][1], ph[2], pl[2]);
            pack_split(accs[2 * ks + 1][2], accs[2 * ks + 1][3], ph[3], pl[3]);
            #pragma unroll
            for (int dg = 0; dg < 4; dg++) {
                uint32_t vm[4], vl4[4];
                uint32_t va = ldm_addr(sKh + 2 * 64 * QLDS, QLDS, ks * 16, dg * 16, lane);
                ldm4t(vm, va);
                ldm4t(vl4, va + 64 * QLDS * 2);
                uint32_t vh0[2] = {vm[0], vm[1]},  vh1[2] = {vm[2], vm[3]};
                uint32_t vl0[2] = {vl4[0], vl4[1]}, vl1[2] = {vl4[2], vl4[3]};
                mma16816(acco[dg * 2 + 0], ph, vh0);
                mma16816(acco[dg * 2 + 0], pl, vh0);
                mma16816(acco[dg * 2 + 0], ph, vl0);
                mma16816(acco[dg * 2 + 1], ph, vh1);
                mma16816(acco[dg * 2 + 1], pl, vh1);
                mma16816(acco[dg * 2 + 1], ph, vl1);
            }
        }
        __syncthreads();
    }

    float inv0 = 1.0f / l0, inv1 = 1.0f / l1;
    int row0 = b * SEQ + q0 + wid * 16 + g;
    #pragma unroll
    for (int dt = 0; dt < 8; dt++) {
        int d = h * DHEAD + dt * 8 + t2;
        uint32_t hv, lv;
        pack_split(acco[dt][0] * inv0, acco[dt][1] * inv0, hv, lv);
        *(uint32_t*)(g_ah + (size_t)row0 * DMODEL + d) = hv;
        *(uint32_t*)(g_al + (size_t)row0 * DMODEL + d) = lv;
        pack_split(acco[dt][2] * inv1, acco[dt][3] * inv1, hv, lv);
        *(uint32_t*)(g_ah + (size_t)(row0 + 8) * DMODEL + d) = hv;
        *(uint32_t*)(g_al + (size_t)(row0 + 8) * DMODEL + d) = lv;
    }
}

// ---------------- launch ----------------
extern "C" void kernel_launch(void* const* d_in, const int* in_sizes, int n_in,
                              void* d_out, int out_size)
{
    const float* hs  = (const float*)d_in[0];
    const float* Wq  = (const float*)d_in[1];
    const float* Wk  = (const float*)d_in[2];
    const float* Wv  = (const float*)d_in[3];
    const float* Wo  = (const float*)d_in[4];
    const float* rel = (const float*)d_in[5];
    float* out = (float*)d_out;

    cudaFuncSetAttribute(mma_gemm, cudaFuncAttributeMaxDynamicSharedMemorySize, GS_BYTES);
    cudaFuncSetAttribute(mma_attn, cudaFuncAttributeMaxDynamicSharedMemorySize, ATT_SMEM);

    bias_kernel<<<16, 256>>>(rel);
    split_a_kernel<<<(MROWS * DMODEL) / (256 * 4), 256>>>(hs);
    dim3 wgrid(32, 32);
    wsplit_kernel<<<wgrid, 256>>>(Wq, 0);
    wsplit_kernel<<<wgrid, 256>>>(Wk, 1);
    wsplit_kernel<<<wgrid, 256>>>(Wv, 2);
    wsplit_kernel<<<wgrid, 256>>>(Wo, 3);

    dim3 ggrid(DMODEL / 128, MROWS / 128);   // (8, 32)
    mma_gemm<<<ggrid, 256, GS_BYTES>>>(out, 1, 0);
    mma_gemm<<<ggrid, 256, GS_BYTES>>>(out, 2, 1);
    mma_gemm<<<ggrid, 256, GS_BYTES>>>(out, 3, 2);

    dim3 agrid(SEQ / 128, NHEAD, BATCH);     // (16, 16, 2)
    mma_attn<<<agrid, 256, ATT_SMEM>>>();

    mma_gemm<<<ggrid, 256, GS_BYTES>>>(out, 0, 3);
}

// round 8
// speedup vs baseline: 2.5932x; 1.0396x over previous
#include <cuda_runtime.h>
#include <cuda_bf16.h>
#include <math.h>
#include <stdint.h>

#define BATCH 2
#define SEQ 2048
#define DMODEL 1024
#define NHEAD 16
#define DHEAD 64
#define MROWS (BATCH*SEQ)          // 4096
#define NBIAS (2*SEQ-1)            // 4095

// ---------------- scratch (device globals; allocation-free) ----------------
__device__ __align__(16) __nv_bfloat16 g_ah[(size_t)MROWS*DMODEL];
__device__ __align__(16) __nv_bfloat16 g_al[(size_t)MROWS*DMODEL];
__device__ __align__(16) __nv_bfloat16 g_wh[(size_t)4*DMODEL*DMODEL];
__device__ __align__(16) __nv_bfloat16 g_wl[(size_t)4*DMODEL*DMODEL];
__device__ __align__(16) __nv_bfloat16 g_qh[(size_t)BATCH*NHEAD*SEQ*DHEAD];
__device__ __align__(16) __nv_bfloat16 g_ql[(size_t)BATCH*NHEAD*SEQ*DHEAD];
__device__ __align__(16) __nv_bfloat16 g_kh[(size_t)BATCH*NHEAD*SEQ*DHEAD];
__device__ __align__(16) __nv_bfloat16 g_kl[(size_t)BATCH*NHEAD*SEQ*DHEAD];
__device__ __align__(16) __nv_bfloat16 g_vh[(size_t)BATCH*NHEAD*SEQ*DHEAD];
__device__ __align__(16) __nv_bfloat16 g_vl[(size_t)BATCH*NHEAD*SEQ*DHEAD];
__device__ float g_bias[NHEAD*NBIAS];

// ---------------- helpers ----------------
__device__ __forceinline__ uint32_t smem_u32(const void* p) {
    return (uint32_t)__cvta_generic_to_shared(p);
}
__device__ __forceinline__ void ldm4(uint32_t* r, uint32_t a) {
    asm volatile("ldmatrix.sync.aligned.m8n8.x4.shared.b16 {%0,%1,%2,%3}, [%4];"
        : "=r"(r[0]), "=r"(r[1]), "=r"(r[2]), "=r"(r[3]) : "r"(a));
}
__device__ __forceinline__ void ldm4t(uint32_t* r, uint32_t a) {
    asm volatile("ldmatrix.sync.aligned.m8n8.x4.trans.shared.b16 {%0,%1,%2,%3}, [%4];"
        : "=r"(r[0]), "=r"(r[1]), "=r"(r[2]), "=r"(r[3]) : "r"(a));
}
__device__ __forceinline__ void mma16816(float* c, const uint32_t* a, const uint32_t* b) {
    asm volatile("mma.sync.aligned.m16n8k16.row.col.f32.bf16.bf16.f32 "
        "{%0,%1,%2,%3}, {%4,%5,%6,%7}, {%8,%9}, {%0,%1,%2,%3};"
        : "+f"(c[0]), "+f"(c[1]), "+f"(c[2]), "+f"(c[3])
        : "r"(a[0]), "r"(a[1]), "r"(a[2]), "r"(a[3]), "r"(b[0]), "r"(b[1]));
}
__device__ __forceinline__ uint32_t ldm_addr(const __nv_bfloat16* base, int lds,
                                             int R0, int C0, int lane) {
    return smem_u32(base + (size_t)(R0 + (lane & 15)) * lds + C0 + ((lane >> 4) << 3));
}
__device__ __forceinline__ void pack_split(float x0, float x1, uint32_t& hi, uint32_t& lo) {
    __nv_bfloat16 h0 = __float2bfloat16_rn(x0), h1 = __float2bfloat16_rn(x1);
    hi = ((uint32_t)__bfloat16_as_ushort(h1) << 16) | (uint32_t)__bfloat16_as_ushort(h0);
    __nv_bfloat16 l0 = __float2bfloat16_rn(x0 - __bfloat162float(h0));
    __nv_bfloat16 l1 = __float2bfloat16_rn(x1 - __bfloat162float(h1));
    lo = ((uint32_t)__bfloat16_as_ushort(l1) << 16) | (uint32_t)__bfloat16_as_ushort(l0);
}
__device__ __forceinline__ void cpasync16(uint32_t dst, const void* src) {
    asm volatile("cp.async.cg.shared.global [%0], [%1], 16;" :: "r"(dst), "l"(src));
}
__device__ __forceinline__ void cpcommit() { asm volatile("cp.async.commit_group;"); }
__device__ __forceinline__ void cpwait0()  { asm volatile("cp.async.wait_group 0;"); }

// ---------------- bias table ----------------
__global__ void bias_kernel(const float* __restrict__ rel_emb)
{
    int idx = blockIdx.x * blockDim.x + threadIdx.x;
    if (idx >= NBIAS) return;
    int rel = idx - (SEQ - 1);
    int bucket = (rel > 0) ? 16 : 0;
    int a = rel < 0 ? -rel : rel;
    if (a < 8) {
        bucket += a;
    } else {
        float t = (logf((float)a / 8.0f) / 2.7725887f) * 8.0f;
        int ti = 8 + (int)t;
        bucket += (ti < 15) ? ti : 15;
    }
    #pragma unroll
    for (int h = 0; h < NHEAD; h++)
        g_bias[h * NBIAS + idx] = rel_emb[bucket * NHEAD + h];
}

// ---------------- split hidden -> g_ah/g_al bf16 ----------------
__global__ __launch_bounds__(256) void split_a_kernel(const float* __restrict__ src)
{
    int i = blockIdx.x * blockDim.x + threadIdx.x;
    float4 x = *(const float4*)(src + (size_t)i * 4);
    uint32_t h0, l0, h1, l1;
    pack_split(x.x, x.y, h0, l0);
    pack_split(x.z, x.w, h1, l1);
    uint2 hh = {h0, h1}, ll = {l0, l1};
    *(uint2*)(g_ah + (size_t)i * 4) = hh;
    *(uint2*)(g_al + (size_t)i * 4) = ll;
}

// ---------------- fused transpose + split of all 4 weights ----------------
__global__ __launch_bounds__(256) void wsplit_kernel(const float* __restrict__ W0,
                                                     const float* __restrict__ W1,
                                                     const float* __restrict__ W2,
                                                     const float* __restrict__ W3)
{
    __shared__ float t[32][33];
    int widx = blockIdx.z;
    const float* W = (widx == 0) ? W0 : (widx == 1) ? W1 : (widx == 2) ? W2 : W3;
    int n0 = blockIdx.x * 32, k0 = blockIdx.y * 32;
    int c = threadIdx.x & 31, r4 = (threadIdx.x >> 5) * 4;
    #pragma unroll
    for (int i = 0; i < 4; i++)
        t[r4 + i][c] = W[(size_t)(k0 + r4 + i) * DMODEL + n0 + c];
    __syncthreads();
    __nv_bfloat16* hi = g_wh + (size_t)widx * DMODEL * DMODEL;
    __nv_bfloat16* lo = g_wl + (size_t)widx * DMODEL * DMODEL;
    #pragma unroll
    for (int i = 0; i < 4; i++) {
        float x = t[c][r4 + i];
        __nv_bfloat16 hb = __float2bfloat16_rn(x);
        size_t o = (size_t)(n0 + r4 + i) * DMODEL + k0 + c;
        hi[o] = hb;
        lo[o] = __float2bfloat16_rn(x - __bfloat162float(hb));
    }
}

// ---------------- pipelined mma.sync bf16-split GEMM ----------------
// mode == -1: fused QKV (grid.z = 3, widx/mode from blockIdx.z)
// mode ==  0: final projection (widx = 3), fp32 out
#define GLDS 40
#define GSTAGE (128 * GLDS)                 // elems per buffer
#define GS_BYTES (2 * 4 * GSTAGE * 2)       // 2 stages x 4 buffers

__global__ __launch_bounds__(256, 2) void mma_gemm(float* __restrict__ outp, int mode)
{
    extern __shared__ __nv_bfloat16 smp[];
    int tid = threadIdx.x, lane = tid & 31, wid = tid >> 5;
    int brow = blockIdx.y, bcol = blockIdx.x;
    int wm = wid & 1, wn = wid >> 1;
    int widx = (mode == -1) ? (int)blockIdx.z : 3;
    int m = (mode == -1) ? (int)blockIdx.z + 1 : 0;

    const __nv_bfloat16* srcs[4];
    srcs[0] = g_ah + (size_t)brow * 128 * DMODEL;
    srcs[1] = g_al + (size_t)brow * 128 * DMODEL;
    srcs[2] = g_wh + (size_t)widx * DMODEL * DMODEL + (size_t)bcol * 128 * DMODEL;
    srcs[3] = g_wl + (size_t)widx * DMODEL * DMODEL + (size_t)bcol * 128 * DMODEL;

    int lbuf[8], lrow[8], lseg[8];
    #pragma unroll
    for (int t = 0; t < 8; t++) {
        int gid = tid + t * 256;
        lbuf[t] = gid >> 9; lrow[t] = (gid >> 2) & 127; lseg[t] = gid & 3;
    }

    float acc[4][4][4];
    #pragma unroll
    for (int i = 0; i < 4; i++)
        #pragma unroll
        for (int j = 0; j < 4; j++)
            #pragma unroll
            for (int k = 0; k < 4; k++) acc[i][j][k] = 0.f;

    // prologue: issue k-slab 0 into stage 0
    #pragma unroll
    for (int t = 0; t < 8; t++) {
        uint32_t dst = smem_u32(&smp[lbuf[t] * GSTAGE + lrow[t] * GLDS + lseg[t] * 8]);
        cpasync16(dst, srcs[lbuf[t]] + (size_t)lrow[t] * DMODEL + lseg[t] * 8);
    }
    cpcommit();

    for (int it = 0; it < DMODEL / 32; it++) {
        int s = it & 1;
        cpwait0();            // stage s data arrived
        __syncthreads();      // all warps: prev compute done, stage s visible
        if (it + 1 < DMODEL / 32) {
            int k0 = (it + 1) * 32;
            #pragma unroll
            for (int t = 0; t < 8; t++) {
                uint32_t dst = smem_u32(&smp[(s ^ 1) * 4 * GSTAGE + lbuf[t] * GSTAGE + lrow[t] * GLDS + lseg[t] * 8]);
                cpasync16(dst, srcs[lbuf[t]] + (size_t)lrow[t] * DMODEL + k0 + lseg[t] * 8);
            }
            cpcommit();
        }

        const __nv_bfloat16* sm = smp + s * 4 * GSTAGE;
        #pragma unroll
        for (int ks = 0; ks < 2; ks++) {
            uint32_t ah[4][4], al[4][4];
            #pragma unroll
            for (int mt = 0; mt < 4; mt++) {
                uint32_t a = ldm_addr(sm, GLDS, wm * 64 + mt * 16, ks * 16, lane);
                ldm4(ah[mt], a);
                ldm4(al[mt], a + GSTAGE * 2);
            }
            #pragma unroll
            for (int ng = 0; ng < 2; ng++) {
                uint32_t bm[4], bl4[4];
                uint32_t ba = ldm_addr(sm + 2 * GSTAGE, GLDS, wn * 32 + ng * 16, ks * 16, lane);
                ldm4(bm, ba);
                ldm4(bl4, ba + GSTAGE * 2);
                uint32_t bh0[2] = {bm[0], bm[2]},  bh1[2] = {bm[1], bm[3]};
                uint32_t bl0[2] = {bl4[0], bl4[2]}, bl1[2] = {bl4[1], bl4[3]};
                #pragma unroll
                for (int mt = 0; mt < 4; mt++) {
                    mma16816(acc[mt][ng * 2 + 0], ah[mt], bh0);
                    mma16816(acc[mt][ng * 2 + 0], al[mt], bh0);
                    mma16816(acc[mt][ng * 2 + 0], ah[mt], bl0);
                    mma16816(acc[mt][ng * 2 + 1], ah[mt], bh1);
                    mma16816(acc[mt][ng * 2 + 1], al[mt], bh1);
                    mma16816(acc[mt][ng * 2 + 1], ah[mt], bl1);
                }
            }
        }
    }

    int g = lane >> 2, t2 = (lane & 3) * 2;
    __nv_bfloat16* dh = (m == 1) ? g_qh : (m == 2) ? g_kh : g_vh;
    __nv_bfloat16* dl = (m == 1) ? g_ql : (m == 2) ? g_kl : g_vl;
    #pragma unroll
    for (int mt = 0; mt < 4; mt++) {
        #pragma unroll
        for (int nt = 0; nt < 4; nt++) {
            int r0  = brow * 128 + wm * 64 + mt * 16 + g;
            int col = bcol * 128 + wn * 32 + nt * 8 + t2;
            float c0 = acc[mt][nt][0], c1 = acc[mt][nt][1];
            float c2 = acc[mt][nt][2], c3 = acc[mt][nt][3];
            if (m == 0) {
                float2 p0 = {c0, c1}, p1 = {c2, c3};
                *(float2*)(outp + (size_t)r0 * DMODEL + col) = p0;
                *(float2*)(outp + (size_t)(r0 + 8) * DMODEL + col) = p1;
            } else {
                int hh = col >> 6, d = col & 63;
                #pragma unroll
                for (int rr = 0; rr < 2; rr++) {
                    int r = r0 + rr * 8;
                    int b = r >> 11, s = r & (SEQ - 1);
                    size_t o = (((size_t)(b * NHEAD + hh) * SEQ) + s) * DHEAD + d;
                    uint32_t hv, lv;
                    pack_split(rr ? c2 : c0, rr ? c3 : c1, hv, lv);
                    *(uint32_t*)(dh + o) = hv;
                    *(uint32_t*)(dl + o) = lv;
                }
            }
        }
    }
}

// ---------------- pipelined mma.sync flash attention ----------------
#define QLDS 72
#define KVSTAGE (4 * 64 * QLDS)   // elems per stage (Kh|Kl|Vh|Vl)
#define ATT_SMEM (2*128*QLDS*2 + 2*KVSTAGE*2 + 2*192*4)

__global__ __launch_bounds__(256, 2) void mma_attn()
{
    extern __shared__ char smemraw[];
    __nv_bfloat16* sQh = (__nv_bfloat16*)smemraw;          // 128 x 72
    __nv_bfloat16* sQl = sQh + 128 * QLDS;
    __nv_bfloat16* sKV = sQl + 128 * QLDS;                 // 2 stages x (Kh|Kl|Vh|Vl)
    float* sBias = (float*)(sKV + 2 * KVSTAGE);            // 2 x 192

    int tid = threadIdx.x, lane = tid & 31, wid = tid >> 5;
    int b = blockIdx.z, h = blockIdx.y, q0 = blockIdx.x * 128;
    size_t bh = (size_t)(b * NHEAD + h) * SEQ;

    const __nv_bfloat16* kvsrc[4] = {g_kh, g_kl, g_vh, g_vl};

    // load Q tile (hi/lo), once
    #pragma unroll
    for (int t = 0; t < 8; t++) {
        int gid = tid + t * 256;
        int buf = gid >> 10, rem = gid & 1023, row = rem >> 3, seg = rem & 7;
        const __nv_bfloat16* src = (buf ? g_ql : g_qh) + (bh + q0 + row) * DHEAD + seg * 8;
        *(uint4*)((buf ? sQl : sQh) + row * QLDS + seg * 8) = *(const uint4*)src;
    }

    int vbuf[8], vrow[8], vseg[8];
    #pragma unroll
    for (int t = 0; t < 8; t++) {
        int gid = tid + t * 256;
        vbuf[t] = gid >> 9; vrow[t] = (gid >> 3) & 63; vseg[t] = gid & 7;
    }

    // prologue: KV tile 0 into stage 0, bias tile 0
    #pragma unroll
    for (int t = 0; t < 8; t++) {
        uint32_t dst = smem_u32(sKV + vbuf[t] * (64 * QLDS) + vrow[t] * QLDS + vseg[t] * 8);
        cpasync16(dst, kvsrc[vbuf[t]] + (bh + vrow[t]) * DHEAD + vseg[t] * 8);
    }
    cpcommit();
    if (tid < 191)
        sBias[tid] = g_bias[h * NBIAS + (SEQ - 1) - q0 - 127 + tid];
    __syncthreads();

    // persistent Q fragments (hi and lo)
    uint32_t qh[4][4], ql[4][4];
    #pragma unroll
    for (int ks = 0; ks < 4; ks++) {
        uint32_t a = ldm_addr(sQh, QLDS, wid * 16, ks * 16, lane);
        ldm4(qh[ks], a);
        ldm4(ql[ks], a + 128 * QLDS * 2);
    }

    int g = lane >> 2, t2 = (lane & 3) * 2;
    int qloc0 = wid * 16 + g, qloc1 = qloc0 + 8;
    float m0 = -1e30f, m1 = -1e30f, l0 = 0.f, l1 = 0.f;
    float acco[8][4];
    #pragma unroll
    for (int i = 0; i < 8; i++)
        #pragma unroll
        for (int j = 0; j < 4; j++) acco[i][j] = 0.f;

    for (int kb = 0; kb < SEQ / 64; kb++) {
        int s = kb & 1;
        cpwait0();            // stage s KV arrived
        __syncthreads();      // all warps: prev compute done, stage s + bias visible
        if (kb + 1 < SEQ / 64) {
            #pragma unroll
            for (int t = 0; t < 8; t++) {
                uint32_t dst = smem_u32(sKV + (s ^ 1) * KVSTAGE + vbuf[t] * (64 * QLDS) + vrow[t] * QLDS + vseg[t] * 8);
                cpasync16(dst, kvsrc[vbuf[t]] + (bh + (kb + 1) * 64 + vrow[t]) * DHEAD + vseg[t] * 8);
            }
            cpcommit();
            if (tid < 191)
                sBias[(s ^ 1) * 192 + tid] = g_bias[h * NBIAS + (SEQ - 1) + (kb + 1) * 64 - q0 - 127 + tid];
        }

        const __nv_bfloat16* sKh = sKV + s * KVSTAGE;
        const float* bias = sBias + s * 192;

        float accs[8][4];
        #pragma unroll
        for (int i = 0; i < 8; i++)
            #pragma unroll
            for (int j = 0; j < 4; j++) accs[i][j] = 0.f;

        #pragma unroll
        for (int ks = 0; ks < 4; ks++) {
            #pragma unroll
            for (int ng = 0; ng < 4; ng++) {
                uint32_t km[4], kl4[4];
                uint32_t ka = ldm_addr(sKh, QLDS, ng * 16, ks * 16, lane);
                ldm4(km, ka);
                ldm4(kl4, ka + 64 * QLDS * 2);
                uint32_t kh0[2] = {km[0], km[2]},  kh1[2] = {km[1], km[3]};
                uint32_t kl0[2] = {kl4[0], kl4[2]}, kl1[2] = {kl4[1], kl4[3]};
                mma16816(accs[ng * 2 + 0], qh[ks], kh0);
                mma16816(accs[ng * 2 + 0], ql[ks], kh0);
                mma16816(accs[ng * 2 + 0], qh[ks], kl0);
                mma16816(accs[ng * 2 + 1], qh[ks], kh1);
                mma16816(accs[ng * 2 + 1], ql[ks], kh1);
                mma16816(accs[ng * 2 + 1], qh[ks], kl1);
            }
        }

        float rmax0 = -1e30f, rmax1 = -1e30f;
        #pragma unroll
        for (int nt = 0; nt < 8; nt++) {
            int c = nt * 8 + t2;
            accs[nt][0] += bias[c + 127 - qloc0];
            accs[nt][1] += bias[c + 128 - qloc0];
            accs[nt][2] += bias[c + 127 - qloc1];
            accs[nt][3] += bias[c + 128 - qloc1];
            rmax0 = fmaxf(rmax0, fmaxf(accs[nt][0], accs[nt][1]));
            rmax1 = fmaxf(rmax1, fmaxf(accs[nt][2], accs[nt][3]));
        }
        rmax0 = fmaxf(rmax0, __shfl_xor_sync(0xffffffffu, rmax0, 1, 4));
        rmax0 = fmaxf(rmax0, __shfl_xor_sync(0xffffffffu, rmax0, 2, 4));
        rmax1 = fmaxf(rmax1, __shfl_xor_sync(0xffffffffu, rmax1, 1, 4));
        rmax1 = fmaxf(rmax1, __shfl_xor_sync(0xffffffffu, rmax1, 2, 4));
        float mn0 = fmaxf(m0, rmax0), mn1 = fmaxf(m1, rmax1);
        float corr0 = __expf(m0 - mn0), corr1 = __expf(m1 - mn1);
        float sum0 = 0.f, sum1 = 0.f;
        #pragma unroll
        for (int nt = 0; nt < 8; nt++) {
            accs[nt][0] = __expf(accs[nt][0] - mn0);
            accs[nt][1] = __expf(accs[nt][1] - mn0);
            accs[nt][2] = __expf(accs[nt][2] - mn1);
            accs[nt][3] = __expf(accs[nt][3] - mn1);
            sum0 += accs[nt][0] + accs[nt][1];
            sum1 += accs[nt][2] + accs[nt][3];
        }
        sum0 += __shfl_xor_sync(0xffffffffu, sum0, 1, 4);
        sum0 += __shfl_xor_sync(0xffffffffu, sum0, 2, 4);
        sum1 += __shfl_xor_sync(0xffffffffu, sum1, 1, 4);
        sum1 += __shfl_xor_sync(0xffffffffu, sum1, 2, 4);
        m0 = mn0; m1 = mn1;
        l0 = l0 * corr0 + sum0;
        l1 = l1 * corr1 + sum1;
        #pragma unroll
        for (int nt = 0; nt < 8; nt++) {
            acco[nt][0] *= corr0; acco[nt][1] *= corr0;
            acco[nt][2] *= corr1; acco[nt][3] *= corr1;
        }

        #pragma unroll
        for (int ks = 0; ks < 4; ks++) {
            uint32_t ph[4], pl[4];
            pack_split(accs[2 * ks][0],     accs[2 * ks][1],     ph[0], pl[0]);
            pack_split(accs[2 * ks][2],     accs[2 * ks][3],     ph[1], pl[1]);
            pack_split(accs[2 * ks + 1][0], accs[2 * ks + 1][1], ph[2], pl[2]);
            pack_split(accs[2 * ks + 1][2], accs[2 * ks + 1][3], ph[3], pl[3]);
            #pragma unroll
            for (int dg = 0; dg < 4; dg++) {
                uint32_t vm[4], vl4[4];
                uint32_t va = ldm_addr(sKh + 2 * 64 * QLDS, QLDS, ks * 16, dg * 16, lane);
                ldm4t(vm, va);
                ldm4t(vl4, va + 64 * QLDS * 2);
                uint32_t vh0[2] = {vm[0], vm[1]},  vh1[2] = {vm[2], vm[3]};
                uint32_t vl0[2] = {vl4[0], vl4[1]}, vl1[2] = {vl4[2], vl4[3]};
                mma16816(acco[dg * 2 + 0], ph, vh0);
                mma16816(acco[dg * 2 + 0], pl, vh0);
                mma16816(acco[dg * 2 + 0], ph, vl0);
                mma16816(acco[dg * 2 + 1], ph, vh1);
                mma16816(acco[dg * 2 + 1], pl, vh1);
                mma16816(acco[dg * 2 + 1], ph, vl1);
            }
        }
    }

    float inv0 = 1.0f / l0, inv1 = 1.0f / l1;
    int row0 = b * SEQ + q0 + wid * 16 + g;
    #pragma unroll
    for (int dt = 0; dt < 8; dt++) {
        int d = h * DHEAD + dt * 8 + t2;
        uint32_t hv, lv;
        pack_split(acco[dt][0] * inv0, acco[dt][1] * inv0, hv, lv);
        *(uint32_t*)(g_ah + (size_t)row0 * DMODEL + d) = hv;
        *(uint32_t*)(g_al + (size_t)row0 * DMODEL + d) = lv;
        pack_split(acco[dt][2] * inv1, acco[dt][3] * inv1, hv, lv);
        *(uint32_t*)(g_ah + (size_t)(row0 + 8) * DMODEL + d) = hv;
        *(uint32_t*)(g_al + (size_t)(row0 + 8) * DMODEL + d) = lv;
    }
}

// ---------------- launch ----------------
extern "C" void kernel_launch(void* const* d_in, const int* in_sizes, int n_in,
                              void* d_out, int out_size)
{
    const float* hs  = (const float*)d_in[0];
    const float* Wq  = (const float*)d_in[1];
    const float* Wk  = (const float*)d_in[2];
    const float* Wv  = (const float*)d_in[3];
    const float* Wo  = (const float*)d_in[4];
    const float* rel = (const float*)d_in[5];
    float* out = (float*)d_out;

    cudaFuncSetAttribute(mma_gemm, cudaFuncAttributeMaxDynamicSharedMemorySize, GS_BYTES);
    cudaFuncSetAttribute(mma_attn, cudaFuncAttributeMaxDynamicSharedMemorySize, ATT_SMEM);

    bias_kernel<<<16, 256>>>(rel);                                   // launch 0
    split_a_kernel<<<(MROWS * DMODEL) / (256 * 4), 256>>>(hs);       // launch 1
    dim3 wgrid(32, 32, 4);
    wsplit_kernel<<<wgrid, 256>>>(Wq, Wk, Wv, Wo);                   // launch 2

    dim3 qkvgrid(DMODEL / 128, MROWS / 128, 3);                      // (8, 32, 3)
    mma_gemm<<<qkvgrid, 256, GS_BYTES>>>(out, -1);                   // launch 3

    dim3 agrid(SEQ / 128, NHEAD, BATCH);                             // (16, 16, 2)
    mma_attn<<<agrid, 256, ATT_SMEM>>>();                            // launch 4

    dim3 ggrid(DMODEL / 128, MROWS / 128);                           // (8, 32)
    mma_gemm<<<ggrid, 256, GS_BYTES>>>(out, 0);                      // launch 5 <- ncu -s 5 lands here
}